// round 5
// baseline (speedup 1.0000x reference)
#include <cuda_runtime.h>
#include <cuda_bf16.h>
#include <math.h>
#include <stdint.h>

// Problem constants (fixed by the dataset)
#define NN   50000
#define EE   800000
#define IND  256
#define HH   4
#define CC   64
#define ETOT (EE + NN)

// ---------------- scratch (static device globals; no allocation) -------------
__device__ __align__(16) float g_h[NN * IND];          // x @ W        51.2 MB
__device__ __align__(16) __nv_bfloat16 g_xh[NN * IND]; // bf16 copy of x 25.6 MB
__device__ __align__(16) float g_asrc[NN * HH];        // per-node src attn
__device__ __align__(16) float g_adst[NN * HH];        // per-node dst attn
__device__ float g_ewsum;                              // sum of edge weights
__device__ __align__(16) float g_K[HH];                // K[h] = <W_edge_h, att_edge_h>
__device__ __align__(16) float g_ex[ETOT * HH];        // exp(alpha) per edge/head
__device__ __align__(16) float g_denom[NN * HH];       // softmax denominators
__device__ __align__(16) float g_acc[NN * CC];         // head-summed aggregation

// ---------------- helpers ----------------------------------------------------
__device__ __forceinline__ uint32_t tf32_rna(float f) {
    uint32_t u;
    asm("cvt.rna.tf32.f32 %0, %1;" : "=r"(u) : "f"(f));
    return u;
}
__device__ __forceinline__ void tf32_split(float f, uint32_t& hi, uint32_t& lo) {
    hi = tf32_rna(f);
    lo = tf32_rna(f - __uint_as_float(hi));
}

#define MMA_TF32(C, A, B)                                                     \
    asm volatile(                                                             \
        "mma.sync.aligned.m16n8k8.row.col.f32.tf32.tf32.f32 "                 \
        "{%0,%1,%2,%3}, {%4,%5,%6,%7}, {%8,%9}, {%0,%1,%2,%3};"               \
        : "+f"((C)[0]), "+f"((C)[1]), "+f"((C)[2]), "+f"((C)[3])              \
        : "r"((A)[0]), "r"((A)[1]), "r"((A)[2]), "r"((A)[3]),                 \
          "r"((B)[0]), "r"((B)[1]))

// ---------------- kernels ----------------------------------------------------

// Zero per-call accumulators (gemm epilogue atomically accumulates attn dots).
__global__ void k_zero() {
    int i = blockIdx.x * blockDim.x + threadIdx.x;
    int stride = gridDim.x * blockDim.x;
    for (int t = i; t < NN * CC; t += stride) g_acc[t] = 0.0f;
    for (int t = i; t < NN * HH; t += stride) {
        g_denom[t] = 0.0f; g_asrc[t] = 0.0f; g_adst[t] = 0.0f;
    }
    if (i == 0) g_ewsum = 0.0f;
}

// K[h] = sum_c W_edge[0, h*64+c] * att_edge[h, c]   (128 threads, warp per head)
__global__ void k_precompK(const float* __restrict__ We, const float* __restrict__ ae) {
    int w = threadIdx.x >> 5, l = threadIdx.x & 31;
    float s = We[w * 64 + l] * ae[w * 64 + l] + We[w * 64 + l + 32] * ae[w * 64 + l + 32];
    #pragma unroll
    for (int o = 16; o; o >>= 1) s += __shfl_xor_sync(0xFFFFFFFFu, s, o);
    if (l == 0) g_K[w] = s;
}

// bf16 copy of x (halves k_ew gather traffic). 4 floats per thread.
__global__ void k_xh(const float* __restrict__ x) {
    int t = blockIdx.x * blockDim.x + threadIdx.x;     // float4 index
    const int total = NN * IND / 4;
    if (t >= total) return;
    float4 v = *(const float4*)&x[(long long)t * 4];
    __nv_bfloat162* o = (__nv_bfloat162*)&g_xh[(long long)t * 4];
    o[0] = __floats2bfloat162_rn(v.x, v.y);
    o[1] = __floats2bfloat162_rn(v.z, v.w);
}

// g_h = x @ W via tensor cores (3xTF32). tf32 hi/lo split is done ONCE at
// smem-fill time; the mainloop is pure LDS + MMA (no ALU cvt work).
// Block tile 128(M) x 64(N), k-chunk 16; blockIdx.x = head (64 cols).
// 8 warps = 4(M) x 2(N); warp tile 32x32 = 2 x 4 mma tiles of m16n8k8.
__global__ void __launch_bounds__(256)
k_gemm(const float* __restrict__ x, const float* __restrict__ W,
       const float* __restrict__ att_src, const float* __restrict__ att_dst) {
    __shared__ uint32_t AsH[128][20];   // [m][k] pad 20 -> conflict-free reads
    __shared__ uint32_t AsL[128][20];
    __shared__ uint32_t BsH[64][20];    // [n][k]
    __shared__ uint32_t BsL[64][20];

    const int tid  = threadIdx.x;
    const int wid  = tid >> 5;
    const int lane = tid & 31;
    const int g    = lane >> 2;     // groupID
    const int t    = lane & 3;      // threadID_in_group
    const int warpM = (wid & 3) * 32;
    const int warpN = (wid >> 2) * 32;
    const int row0 = blockIdx.y * 128;
    const int head = blockIdx.x;
    const int col0 = head * 64;

    float acc[2][4][4] = {};

    for (int k0 = 0; k0 < IND; k0 += 16) {
        // --- A tile: 128 x 16 floats (512 float4, 2 per thread), split tf32 ---
        #pragma unroll
        for (int p = 0; p < 2; p++) {
            int f = tid + p * 256;
            int r = f >> 2, c4 = (f & 3) * 4;
            float4 v = make_float4(0.f, 0.f, 0.f, 0.f);
            if (row0 + r < NN)
                v = *(const float4*)&x[(long long)(row0 + r) * IND + k0 + c4];
            tf32_split(v.x, AsH[r][c4 + 0], AsL[r][c4 + 0]);
            tf32_split(v.y, AsH[r][c4 + 1], AsL[r][c4 + 1]);
            tf32_split(v.z, AsH[r][c4 + 2], AsL[r][c4 + 2]);
            tf32_split(v.w, AsH[r][c4 + 3], AsL[r][c4 + 3]);
        }
        // --- B tile: 16 x 64 floats (256 float4, 1 per thread), transpose+split ---
        {
            int kr = tid >> 4, c4 = (tid & 15) * 4;
            float4 v = *(const float4*)&W[(long long)(k0 + kr) * IND + col0 + c4];
            tf32_split(v.x, BsH[c4 + 0][kr], BsL[c4 + 0][kr]);
            tf32_split(v.y, BsH[c4 + 1][kr], BsL[c4 + 1][kr]);
            tf32_split(v.z, BsH[c4 + 2][kr], BsL[c4 + 2][kr]);
            tf32_split(v.w, BsH[c4 + 3][kr], BsL[c4 + 3][kr]);
        }
        __syncthreads();

        #pragma unroll
        for (int ks = 0; ks < 2; ks++) {
            const int k = ks * 8;
            uint32_t ahi[2][4], alo[2][4];
            #pragma unroll
            for (int i = 0; i < 2; i++) {
                int m = warpM + i * 16 + g;
                ahi[i][0] = AsH[m][k + t];         alo[i][0] = AsL[m][k + t];
                ahi[i][1] = AsH[m + 8][k + t];     alo[i][1] = AsL[m + 8][k + t];
                ahi[i][2] = AsH[m][k + t + 4];     alo[i][2] = AsL[m][k + t + 4];
                ahi[i][3] = AsH[m + 8][k + t + 4]; alo[i][3] = AsL[m + 8][k + t + 4];
            }
            uint32_t bhi[4][2], blo[4][2];
            #pragma unroll
            for (int j = 0; j < 4; j++) {
                int n = warpN + j * 8 + g;
                bhi[j][0] = BsH[n][k + t];     blo[j][0] = BsL[n][k + t];
                bhi[j][1] = BsH[n][k + t + 4]; blo[j][1] = BsL[n][k + t + 4];
            }
            #pragma unroll
            for (int i = 0; i < 2; i++)
                #pragma unroll
                for (int j = 0; j < 4; j++) {
                    MMA_TF32(acc[i][j], ahi[i], bhi[j]);
                    MMA_TF32(acc[i][j], ahi[i], blo[j]);
                    MMA_TF32(acc[i][j], alo[i], bhi[j]);
                }
        }
        __syncthreads();
    }

    // --- epilogue: store h + fused attention dot products ---
    float asv[4][2], adv[4][2];
    #pragma unroll
    for (int j = 0; j < 4; j++) {
        int cb = col0 + warpN + j * 8 + 2 * t;
        asv[j][0] = att_src[cb]; asv[j][1] = att_src[cb + 1];
        adv[j][0] = att_dst[cb]; adv[j][1] = att_dst[cb + 1];
    }
    #pragma unroll
    for (int i = 0; i < 2; i++) {
        int r0 = row0 + warpM + i * 16 + g;
        int r1 = r0 + 8;
        float ps0 = 0.f, pd0 = 0.f, ps1 = 0.f, pd1 = 0.f;
        #pragma unroll
        for (int j = 0; j < 4; j++) {
            int cb = col0 + warpN + j * 8 + 2 * t;
            if (r0 < NN)
                *(float2*)&g_h[(long long)r0 * IND + cb] =
                    make_float2(acc[i][j][0], acc[i][j][1]);
            if (r1 < NN)
                *(float2*)&g_h[(long long)r1 * IND + cb] =
                    make_float2(acc[i][j][2], acc[i][j][3]);
            ps0 += acc[i][j][0] * asv[j][0] + acc[i][j][1] * asv[j][1];
            pd0 += acc[i][j][0] * adv[j][0] + acc[i][j][1] * adv[j][1];
            ps1 += acc[i][j][2] * asv[j][0] + acc[i][j][3] * asv[j][1];
            pd1 += acc[i][j][2] * adv[j][0] + acc[i][j][3] * adv[j][1];
        }
        #pragma unroll
        for (int o = 1; o <= 2; o <<= 1) {
            ps0 += __shfl_xor_sync(0xFFFFFFFFu, ps0, o);
            pd0 += __shfl_xor_sync(0xFFFFFFFFu, pd0, o);
            ps1 += __shfl_xor_sync(0xFFFFFFFFu, ps1, o);
            pd1 += __shfl_xor_sync(0xFFFFFFFFu, pd1, o);
        }
        if (t == 0) {
            if (r0 < NN) {
                atomicAdd(&g_asrc[r0 * HH + head], ps0);
                atomicAdd(&g_adst[r0 * HH + head], pd0);
            }
            if (r1 < NN) {
                atomicAdd(&g_asrc[r1 * HH + head], ps1);
                atomicAdd(&g_adst[r1 * HH + head], pd1);
            }
        }
    }
}

// Fused edge pass: ew = exp(-||x_s-x_d||) (warp reduction, bf16 rows), then
// lane 0 computes ex = exp(leaky_relu(a_src[s]+a_dst[d]+ew*K)) and denom +=.
// No segment-max: alpha is O(10); softmax is shift-invariant.
__global__ void k_ew(const int* __restrict__ ei) {
    __shared__ float ssum[8];
    int warp = threadIdx.x >> 5, lane = threadIdx.x & 31;
    long long e = (long long)blockIdx.x * 8 + warp;
    float w = 0.0f;
    int s = 0, d = 0;
    if (e < EE) {
        s = ei[e]; d = ei[EE + e];
        const uint4* xs = (const uint4*)&g_xh[(long long)s * IND];
        const uint4* xd = (const uint4*)&g_xh[(long long)d * IND];
        uint4 a = xs[lane], b = xd[lane];
        float acc = 0.0f;
        #pragma unroll
        for (int i = 0; i < 4; i++) {
            unsigned int ua = (&a.x)[i], ub = (&b.x)[i];
            float2 fa = __bfloat1622float2(*(__nv_bfloat162*)&ua);
            float2 fb = __bfloat1622float2(*(__nv_bfloat162*)&ub);
            float d0 = fa.x - fb.x, d1 = fa.y - fb.y;
            acc += d0 * d0 + d1 * d1;
        }
        #pragma unroll
        for (int o = 16; o; o >>= 1) acc += __shfl_xor_sync(0xFFFFFFFFu, acc, o);
        w = expf(-sqrtf(acc));
    }
    if (lane == 0) {
        ssum[warp] = (e < EE) ? w : 0.0f;
        if (e < EE) {
            float4 as4 = *(const float4*)&g_asrc[s * HH];
            float4 ad4 = *(const float4*)&g_adst[d * HH];
            float4 k4  = *(const float4*)&g_K[0];
            float a0 = as4.x + ad4.x + w * k4.x;
            float a1 = as4.y + ad4.y + w * k4.y;
            float a2 = as4.z + ad4.z + w * k4.z;
            float a3 = as4.w + ad4.w + w * k4.w;
            float e0 = expf(a0 > 0.f ? a0 : 0.2f * a0);
            float e1 = expf(a1 > 0.f ? a1 : 0.2f * a1);
            float e2 = expf(a2 > 0.f ? a2 : 0.2f * a2);
            float e3 = expf(a3 > 0.f ? a3 : 0.2f * a3);
            *(float4*)&g_ex[e * HH] = make_float4(e0, e1, e2, e3);
            atomicAdd(&g_denom[d * HH + 0], e0);
            atomicAdd(&g_denom[d * HH + 1], e1);
            atomicAdd(&g_denom[d * HH + 2], e2);
            atomicAdd(&g_denom[d * HH + 3], e3);
        }
    }
    __syncthreads();
    if (threadIdx.x == 0) {
        float t = 0.0f;
        #pragma unroll
        for (int i = 0; i < 8; i++) t += ssum[i];
        atomicAdd(&g_ewsum, t);
    }
}

// Self-loop edges: ew = mean over real edges; same alpha/ex/denom update.
__global__ void k_self() {
    int n = blockIdx.x * blockDim.x + threadIdx.x;
    if (n >= NN) return;
    float w = g_ewsum * (1.0f / (float)EE);
    float4 as4 = *(const float4*)&g_asrc[n * HH];
    float4 ad4 = *(const float4*)&g_adst[n * HH];
    float4 k4  = *(const float4*)&g_K[0];
    float a0 = as4.x + ad4.x + w * k4.x;
    float a1 = as4.y + ad4.y + w * k4.y;
    float a2 = as4.z + ad4.z + w * k4.z;
    float a3 = as4.w + ad4.w + w * k4.w;
    float e0 = expf(a0 > 0.f ? a0 : 0.2f * a0);
    float e1 = expf(a1 > 0.f ? a1 : 0.2f * a1);
    float e2 = expf(a2 > 0.f ? a2 : 0.2f * a2);
    float e3 = expf(a3 > 0.f ? a3 : 0.2f * a3);
    *(float4*)&g_ex[(long long)(EE + n) * HH] = make_float4(e0, e1, e2, e3);
    atomicAdd(&g_denom[n * HH + 0], e0);
    atomicAdd(&g_denom[n * HH + 1], e1);
    atomicAdd(&g_denom[n * HH + 2], e2);
    atomicAdd(&g_denom[n * HH + 3], e3);
}

// acc[dst, c] += sum_h (ex/denom) * h[src, h, c]  — half-warp per edge,
// heads reduced in registers before the vector atomic (64 floats/edge).
__global__ void k_agg(const int* __restrict__ ei) {
    int tid = threadIdx.x;
    long long e = (long long)blockIdx.x * 16 + (tid >> 4);
    if (e >= ETOT) return;
    int lane16 = tid & 15;
    int s, d;
    if (e < EE) { s = ei[e]; d = ei[EE + e]; }
    else        { s = d = (int)(e - EE); }
    float4 ex4 = *(const float4*)&g_ex[e * HH];
    float4 dn4 = *(const float4*)&g_denom[d * HH];
    float w0 = ex4.x / (dn4.x + 1e-16f);
    float w1 = ex4.y / (dn4.y + 1e-16f);
    float w2 = ex4.z / (dn4.z + 1e-16f);
    float w3 = ex4.w / (dn4.w + 1e-16f);
    const float* hr = &g_h[(long long)s * IND];
    int c0 = lane16 * 4;
    float4 h0 = *(const float4*)&hr[0 * 64 + c0];
    float4 h1 = *(const float4*)&hr[1 * 64 + c0];
    float4 h2 = *(const float4*)&hr[2 * 64 + c0];
    float4 h3 = *(const float4*)&hr[3 * 64 + c0];
    float vx = w0 * h0.x + w1 * h1.x + w2 * h2.x + w3 * h3.x;
    float vy = w0 * h0.y + w1 * h1.y + w2 * h2.y + w3 * h3.y;
    float vz = w0 * h0.z + w1 * h1.z + w2 * h2.z + w3 * h3.z;
    float vw = w0 * h0.w + w1 * h1.w + w2 * h2.w + w3 * h3.w;
    float* dst = &g_acc[(long long)d * CC + c0];
    asm volatile("red.global.add.v4.f32 [%0], {%1, %2, %3, %4};"
                 :: "l"(dst), "f"(vx), "f"(vy), "f"(vz), "f"(vw) : "memory");
}

// out[n,c] = relu(acc[n,c]/H + bias[c])
__global__ void k_final(const float* __restrict__ bias, float* __restrict__ out) {
    int t = blockIdx.x * blockDim.x + threadIdx.x;
    if (t >= NN * CC) return;
    int c = t & (CC - 1);
    float v = g_acc[t] * (1.0f / (float)HH) + bias[c];
    out[t] = v > 0.0f ? v : 0.0f;
}

// ---------------- launch ------------------------------------------------------
extern "C" void kernel_launch(void* const* d_in, const int* in_sizes, int n_in,
                              void* d_out, int out_size) {
    const float* x        = (const float*)d_in[0];
    const int*   ei       = (const int*)d_in[1];     // int32 (JAX x64 disabled)
    const float* W        = (const float*)d_in[2];
    const float* att_src  = (const float*)d_in[3];
    const float* att_dst  = (const float*)d_in[4];
    const float* W_edge   = (const float*)d_in[5];
    const float* att_edge = (const float*)d_in[6];
    const float* bias     = (const float*)d_in[7];
    float*       out      = (float*)d_out;
    (void)in_sizes; (void)n_in; (void)out_size;

    k_zero<<<1024, 256>>>();
    k_precompK<<<1, 128>>>(W_edge, att_edge);
    k_xh<<<(NN * IND / 4 + 255) / 256, 256>>>(x);
    k_gemm<<<dim3(HH, (NN + 127) / 128), 256>>>(x, W, att_src, att_dst);
    k_ew<<<(EE + 7) / 8, 256>>>(ei);
    k_self<<<(NN + 255) / 256, 256>>>();
    k_agg<<<(ETOT + 15) / 16, 256>>>(ei);
    k_final<<<(NN * CC + 255) / 256, 256>>>(bias, out);
}

// round 7
// speedup vs baseline: 1.3052x; 1.3052x over previous
#include <cuda_runtime.h>
#include <cuda_bf16.h>
#include <math.h>
#include <stdint.h>

// Problem constants (fixed by the dataset)
#define NN   50000
#define EE   800000
#define IND  256
#define HH   4
#define CC   64
#define ETOT (EE + NN)
#define KP   (IND / 2)          // 128 bf16 pairs per row

// ---------------- scratch (static device globals; no allocation) -------------
__device__ __align__(16) float g_h[NN * IND];          // x @ W        51.2 MB
__device__ __align__(16) __nv_bfloat16 g_xh[NN * IND]; // bf16 hi of x 25.6 MB
__device__ __align__(16) __nv_bfloat16 g_xl[NN * IND]; // bf16 lo of x 25.6 MB
__device__ __align__(16) uint32_t g_WtH[HH][CC][KP];   // W hi, [head][n][kpair]
__device__ __align__(16) uint32_t g_WtL[HH][CC][KP];   // W lo
__device__ __align__(16) float g_asrc[NN * HH];        // per-node src attn
__device__ __align__(16) float g_adst[NN * HH];        // per-node dst attn
__device__ float g_ewsum;                              // sum of edge weights
__device__ __align__(16) float g_K[HH];                // K[h] = <W_edge_h, att_edge_h>
__device__ __align__(16) float g_ex[ETOT * HH];        // exp(alpha) per edge/head
__device__ __align__(16) float g_denom[NN * HH];       // softmax denominators
__device__ __align__(16) float g_acc[NN * CC];         // head-summed aggregation

// ---------------- helpers ----------------------------------------------------
__device__ __forceinline__ void bf16_split(float f, __nv_bfloat16& hi, __nv_bfloat16& lo) {
    hi = __float2bfloat16_rn(f);
    lo = __float2bfloat16_rn(f - __bfloat162float(hi));
}

#define MMA_BF16(C, A, B)                                                     \
    asm volatile(                                                             \
        "mma.sync.aligned.m16n8k16.row.col.f32.bf16.bf16.f32 "                \
        "{%0,%1,%2,%3}, {%4,%5,%6,%7}, {%8,%9}, {%0,%1,%2,%3};"               \
        : "+f"((C)[0]), "+f"((C)[1]), "+f"((C)[2]), "+f"((C)[3])              \
        : "r"((A)[0]), "r"((A)[1]), "r"((A)[2]), "r"((A)[3]),                 \
          "r"((B)[0]), "r"((B)[1]))

// ---------------- kernels ----------------------------------------------------

__global__ void k_zero() {
    int i = blockIdx.x * blockDim.x + threadIdx.x;
    int stride = gridDim.x * blockDim.x;
    for (int t = i; t < NN * CC; t += stride) g_acc[t] = 0.0f;
    for (int t = i; t < NN * HH; t += stride) {
        g_denom[t] = 0.0f; g_asrc[t] = 0.0f; g_adst[t] = 0.0f;
    }
    if (i == 0) g_ewsum = 0.0f;
}

// K[h] = sum_c W_edge[0, h*64+c] * att_edge[h, c]
__global__ void k_precompK(const float* __restrict__ We, const float* __restrict__ ae) {
    int w = threadIdx.x >> 5, l = threadIdx.x & 31;
    float s = We[w * 64 + l] * ae[w * 64 + l] + We[w * 64 + l + 32] * ae[w * 64 + l + 32];
    #pragma unroll
    for (int o = 16; o; o >>= 1) s += __shfl_xor_sync(0xFFFFFFFFu, s, o);
    if (l == 0) g_K[w] = s;
}

// x -> bf16 hi + bf16 lo (used by gemm and k_ew)
__global__ void k_prep(const float* __restrict__ x) {
    int t = blockIdx.x * blockDim.x + threadIdx.x;     // float4 index
    const int total = NN * IND / 4;
    if (t >= total) return;
    float4 v = *(const float4*)&x[(long long)t * 4];
    __nv_bfloat16 h[4], l[4];
    bf16_split(v.x, h[0], l[0]); bf16_split(v.y, h[1], l[1]);
    bf16_split(v.z, h[2], l[2]); bf16_split(v.w, h[3], l[3]);
    *(uint2*)&g_xh[(long long)t * 4] = *(uint2*)h;
    *(uint2*)&g_xl[(long long)t * 4] = *(uint2*)l;
}

// W -> transposed packed bf16 hi/lo: Wt[head][n][kpair] = pack(W[2kp][c], W[2kp+1][c])
__global__ void k_prepW(const float* __restrict__ W) {
    int idx = blockIdx.x * blockDim.x + threadIdx.x;   // [head][n][kp] flat
    if (idx >= HH * CC * KP) return;
    int kp = idx & (KP - 1);
    int n  = (idx >> 7) & (CC - 1);
    int hd = idx >> 13;
    int col = hd * CC + n;
    float w0 = W[(2 * kp) * IND + col];
    float w1 = W[(2 * kp + 1) * IND + col];
    __nv_bfloat16 h0, l0, h1, l1;
    bf16_split(w0, h0, l0); bf16_split(w1, h1, l1);
    __nv_bfloat16 hp[2] = {h0, h1}, lp[2] = {l0, l1};
    g_WtH[hd][n][kp] = *(uint32_t*)hp;
    g_WtL[hd][n][kp] = *(uint32_t*)lp;
}

// g_h = x @ W via bf16 double-split tensor-core GEMM (m16n8k16, 3 products).
// Block tile 128(M) x 64(N), k-chunk 32; blockIdx.x = head.
// 8 warps = 4(M) x 2(N); warp tile 32x32 = 2 x 4 mma tiles.
// Mainloop: pure uint4 fill + LDS.32 + MMA. Fused attention-dot epilogue.
#define SPAD 20
__global__ void __launch_bounds__(256)
k_gemm(const float* __restrict__ att_src, const float* __restrict__ att_dst) {
    __shared__ uint32_t AsH[128][SPAD];   // [m][kpair] (16 pairs used)
    __shared__ uint32_t AsL[128][SPAD];
    __shared__ uint32_t BsH[64][SPAD];    // [n][kpair]
    __shared__ uint32_t BsL[64][SPAD];

    const int tid  = threadIdx.x;
    const int wid  = tid >> 5;
    const int lane = tid & 31;
    const int g    = lane >> 2;
    const int t    = lane & 3;
    const int warpM = (wid & 3) * 32;
    const int warpN = (wid >> 2) * 32;
    const int row0 = blockIdx.y * 128;
    const int head = blockIdx.x;
    const int col0 = head * CC;

    float acc[2][4][4] = {};

    for (int k0 = 0; k0 < KP; k0 += 16) {       // 16 kpairs = 32 k per chunk
        // A fill: 128 rows x 4 uint4 (hi+lo) -> 2 per thread each
        #pragma unroll
        for (int p = 0; p < 2; p++) {
            int f = tid + p * 256;
            int r = f >> 2, q = f & 3;
            long long src = (long long)(row0 + r) * IND + k0 * 2;
            uint4 vh = make_uint4(0, 0, 0, 0), vl = make_uint4(0, 0, 0, 0);
            if (row0 + r < NN) {
                vh = ((const uint4*)&g_xh[src])[q];
                vl = ((const uint4*)&g_xl[src])[q];
            }
            *(uint4*)&AsH[r][q * 4] = vh;
            *(uint4*)&AsL[r][q * 4] = vl;
        }
        // B fill: 64 rows x 4 uint4 -> 1 per thread each
        {
            int n = tid >> 2, q = tid & 3;
            *(uint4*)&BsH[n][q * 4] = ((const uint4*)&g_WtH[head][n][k0])[q];
            *(uint4*)&BsL[n][q * 4] = ((const uint4*)&g_WtL[head][n][k0])[q];
        }
        __syncthreads();

        #pragma unroll
        for (int s = 0; s < 2; s++) {            // two k16 steps per chunk
            const int kb = s * 8;
            uint32_t ah[2][4], al[2][4];
            #pragma unroll
            for (int i = 0; i < 2; i++) {
                int m = warpM + i * 16 + g;
                ah[i][0] = AsH[m][kb + t];     al[i][0] = AsL[m][kb + t];
                ah[i][1] = AsH[m + 8][kb + t]; al[i][1] = AsL[m + 8][kb + t];
                ah[i][2] = AsH[m][kb + t + 4];     al[i][2] = AsL[m][kb + t + 4];
                ah[i][3] = AsH[m + 8][kb + t + 4]; al[i][3] = AsL[m + 8][kb + t + 4];
            }
            uint32_t bh[4][2], bl[4][2];
            #pragma unroll
            for (int j = 0; j < 4; j++) {
                int n = warpN + j * 8 + g;
                bh[j][0] = BsH[n][kb + t];     bl[j][0] = BsL[n][kb + t];
                bh[j][1] = BsH[n][kb + t + 4]; bl[j][1] = BsL[n][kb + t + 4];
            }
            #pragma unroll
            for (int i = 0; i < 2; i++)
                #pragma unroll
                for (int j = 0; j < 4; j++) {
                    MMA_BF16(acc[i][j], ah[i], bh[j]);
                    MMA_BF16(acc[i][j], ah[i], bl[j]);
                    MMA_BF16(acc[i][j], al[i], bh[j]);
                }
        }
        __syncthreads();
    }

    // --- epilogue: store h + fused attention dot products ---
    float asv[4][2], adv[4][2];
    #pragma unroll
    for (int j = 0; j < 4; j++) {
        int cb = col0 + warpN + j * 8 + 2 * t;
        asv[j][0] = att_src[cb]; asv[j][1] = att_src[cb + 1];
        adv[j][0] = att_dst[cb]; adv[j][1] = att_dst[cb + 1];
    }
    #pragma unroll
    for (int i = 0; i < 2; i++) {
        int r0 = row0 + warpM + i * 16 + g;
        int r1 = r0 + 8;
        float ps0 = 0.f, pd0 = 0.f, ps1 = 0.f, pd1 = 0.f;
        #pragma unroll
        for (int j = 0; j < 4; j++) {
            int cb = col0 + warpN + j * 8 + 2 * t;
            if (r0 < NN)
                *(float2*)&g_h[(long long)r0 * IND + cb] =
                    make_float2(acc[i][j][0], acc[i][j][1]);
            if (r1 < NN)
                *(float2*)&g_h[(long long)r1 * IND + cb] =
                    make_float2(acc[i][j][2], acc[i][j][3]);
            ps0 += acc[i][j][0] * asv[j][0] + acc[i][j][1] * asv[j][1];
            pd0 += acc[i][j][0] * adv[j][0] + acc[i][j][1] * adv[j][1];
            ps1 += acc[i][j][2] * asv[j][0] + acc[i][j][3] * asv[j][1];
            pd1 += acc[i][j][2] * adv[j][0] + acc[i][j][3] * adv[j][1];
        }
        #pragma unroll
        for (int o = 1; o <= 2; o <<= 1) {
            ps0 += __shfl_xor_sync(0xFFFFFFFFu, ps0, o);
            pd0 += __shfl_xor_sync(0xFFFFFFFFu, pd0, o);
            ps1 += __shfl_xor_sync(0xFFFFFFFFu, ps1, o);
            pd1 += __shfl_xor_sync(0xFFFFFFFFu, pd1, o);
        }
        if (t == 0) {
            if (r0 < NN) {
                atomicAdd(&g_asrc[r0 * HH + head], ps0);
                atomicAdd(&g_adst[r0 * HH + head], pd0);
            }
            if (r1 < NN) {
                atomicAdd(&g_asrc[r1 * HH + head], ps1);
                atomicAdd(&g_adst[r1 * HH + head], pd1);
            }
        }
    }
}

// Fused edge pass: warp computes ew; lanes 0-3 each finish one head
// (alpha -> ex -> denom atomic), lane h also stores g_ex[e*4+h].
__global__ void k_ew(const int* __restrict__ ei) {
    __shared__ float ssum[8];
    int warp = threadIdx.x >> 5, lane = threadIdx.x & 31;
    long long e = (long long)blockIdx.x * 8 + warp;
    float w = 0.0f;
    int s = 0, d = 0;
    if (e < EE) {
        s = ei[e]; d = ei[EE + e];
        const uint4* xs = (const uint4*)&g_xh[(long long)s * IND];
        const uint4* xd = (const uint4*)&g_xh[(long long)d * IND];
        uint4 a = xs[lane], b = xd[lane];
        float acc = 0.0f;
        #pragma unroll
        for (int i = 0; i < 4; i++) {
            unsigned int ua = (&a.x)[i], ub = (&b.x)[i];
            float2 fa = __bfloat1622float2(*(__nv_bfloat162*)&ua);
            float2 fb = __bfloat1622float2(*(__nv_bfloat162*)&ub);
            float d0 = fa.x - fb.x, d1 = fa.y - fb.y;
            acc += d0 * d0 + d1 * d1;
        }
        #pragma unroll
        for (int o = 16; o; o >>= 1) acc += __shfl_xor_sync(0xFFFFFFFFu, acc, o);
        w = expf(-sqrtf(acc));
        if (lane < HH) {                          // lanes 0-3: one head each
            float a_h = g_asrc[s * HH + lane] + g_adst[d * HH + lane] + w * g_K[lane];
            float v = (a_h > 0.f) ? a_h : 0.2f * a_h;
            float ex = expf(v);
            g_ex[e * HH + lane] = ex;
            atomicAdd(&g_denom[d * HH + lane], ex);
        }
    }
    if (lane == 0) ssum[warp] = (e < EE) ? w : 0.0f;
    __syncthreads();
    if (threadIdx.x == 0) {
        float t = 0.0f;
        #pragma unroll
        for (int i = 0; i < 8; i++) t += ssum[i];
        atomicAdd(&g_ewsum, t);
    }
}

// Self-loop edges: ew = mean over real edges.
__global__ void k_self() {
    int n = blockIdx.x * blockDim.x + threadIdx.x;
    if (n >= NN) return;
    float w = g_ewsum * (1.0f / (float)EE);
    float4 as4 = *(const float4*)&g_asrc[n * HH];
    float4 ad4 = *(const float4*)&g_adst[n * HH];
    float4 k4  = *(const float4*)&g_K[0];
    float a0 = as4.x + ad4.x + w * k4.x;
    float a1 = as4.y + ad4.y + w * k4.y;
    float a2 = as4.z + ad4.z + w * k4.z;
    float a3 = as4.w + ad4.w + w * k4.w;
    float e0 = expf(a0 > 0.f ? a0 : 0.2f * a0);
    float e1 = expf(a1 > 0.f ? a1 : 0.2f * a1);
    float e2 = expf(a2 > 0.f ? a2 : 0.2f * a2);
    float e3 = expf(a3 > 0.f ? a3 : 0.2f * a3);
    *(float4*)&g_ex[(long long)(EE + n) * HH] = make_float4(e0, e1, e2, e3);
    atomicAdd(&g_denom[n * HH + 0], e0);
    atomicAdd(&g_denom[n * HH + 1], e1);
    atomicAdd(&g_denom[n * HH + 2], e2);
    atomicAdd(&g_denom[n * HH + 3], e3);
}

// acc[dst, c] += sum_h (ex/denom) * h[src, h, c]
__global__ void k_agg(const int* __restrict__ ei) {
    int tid = threadIdx.x;
    long long e = (long long)blockIdx.x * 16 + (tid >> 4);
    if (e >= ETOT) return;
    int lane16 = tid & 15;
    int s, d;
    if (e < EE) { s = ei[e]; d = ei[EE + e]; }
    else        { s = d = (int)(e - EE); }
    float4 ex4 = *(const float4*)&g_ex[e * HH];
    float4 dn4 = *(const float4*)&g_denom[d * HH];
    float w0 = ex4.x / (dn4.x + 1e-16f);
    float w1 = ex4.y / (dn4.y + 1e-16f);
    float w2 = ex4.z / (dn4.z + 1e-16f);
    float w3 = ex4.w / (dn4.w + 1e-16f);
    const float* hr = &g_h[(long long)s * IND];
    int c0 = lane16 * 4;
    float4 h0 = *(const float4*)&hr[0 * 64 + c0];
    float4 h1 = *(const float4*)&hr[1 * 64 + c0];
    float4 h2 = *(const float4*)&hr[2 * 64 + c0];
    float4 h3 = *(const float4*)&hr[3 * 64 + c0];
    float vx = w0 * h0.x + w1 * h1.x + w2 * h2.x + w3 * h3.x;
    float vy = w0 * h0.y + w1 * h1.y + w2 * h2.y + w3 * h3.y;
    float vz = w0 * h0.z + w1 * h1.z + w2 * h2.z + w3 * h3.z;
    float vw = w0 * h0.w + w1 * h1.w + w2 * h2.w + w3 * h3.w;
    float* dst = &g_acc[(long long)d * CC + c0];
    asm volatile("red.global.add.v4.f32 [%0], {%1, %2, %3, %4};"
                 :: "l"(dst), "f"(vx), "f"(vy), "f"(vz), "f"(vw) : "memory");
}

// out[n,c] = relu(acc[n,c]/H + bias[c])
__global__ void k_final(const float* __restrict__ bias, float* __restrict__ out) {
    int t = blockIdx.x * blockDim.x + threadIdx.x;
    if (t >= NN * CC) return;
    int c = t & (CC - 1);
    float v = g_acc[t] * (1.0f / (float)HH) + bias[c];
    out[t] = v > 0.0f ? v : 0.0f;
}

// ---------------- launch ------------------------------------------------------
extern "C" void kernel_launch(void* const* d_in, const int* in_sizes, int n_in,
                              void* d_out, int out_size) {
    const float* x        = (const float*)d_in[0];
    const int*   ei       = (const int*)d_in[1];     // int32 (JAX x64 disabled)
    const float* W        = (const float*)d_in[2];
    const float* att_src  = (const float*)d_in[3];
    const float* att_dst  = (const float*)d_in[4];
    const float* W_edge   = (const float*)d_in[5];
    const float* att_edge = (const float*)d_in[6];
    const float* bias     = (const float*)d_in[7];
    float*       out      = (float*)d_out;
    (void)in_sizes; (void)n_in; (void)out_size;

    k_zero<<<1024, 256>>>();
    k_precompK<<<1, 128>>>(W_edge, att_edge);
    k_prep<<<(NN * IND / 4 + 255) / 256, 256>>>(x);
    k_prepW<<<(HH * CC * KP + 255) / 256, 256>>>(W);
    k_gemm<<<dim3(HH, (NN + 127) / 128), 256>>>(att_src, att_dst);
    k_ew<<<(EE + 7) / 8, 256>>>(ei);
    k_self<<<(NN + 255) / 256, 256>>>();
    k_agg<<<(ETOT + 15) / 16, 256>>>(ei);
    k_final<<<(NN * CC + 255) / 256, 256>>>(bias, out);
}